// round 1
// baseline (speedup 1.0000x reference)
#include <cuda_runtime.h>
#include <cuda_bf16.h>
#include <math.h>

#define L_SEQ   1024
#define BATCH   2
#define DMODEL  1024
#define DINNER  2048
#define NHEADS  32
#define HEADDIM 64
#define DSTATE  64
#define CONVDIM 2176
#define DINPROJ 4256
#define M_ROWS  2048   // BATCH * L_SEQ

// ---------------- scratch (device globals; no allocation allowed) ----------
__device__ float g_xflip[M_ROWS * DMODEL];
__device__ float g_zx[2][M_ROWS * DINPROJ];     // in_proj outputs, local time
__device__ float g_xbc[2][M_ROWS * CONVDIM];    // conv+silu output
__device__ float g_dt[2][M_ROWS * NHEADS];
__device__ float g_dA[2][M_ROWS * NHEADS];
__device__ float g_y[2][M_ROWS * DINNER];       // scan out -> gated/normed in place
__device__ float g_dirout[2][M_ROWS * DMODEL];  // per-dir out_proj result (local time)
__device__ float g_cat[M_ROWS * DINNER];        // concat(fwd, flip(bwd))
__device__ float g_hbuf[M_ROWS * DMODEL];       // final proj result (pre residual/LN)

// ---------------- flip x along sequence (build local-time input for bwd) ---
__global__ void flip_copy(const float* __restrict__ x) {
    int row = blockIdx.x;                 // local row: b*L + tau
    int b = row >> 10, t = row & 1023;
    int src = (b << 10) + (1023 - t);
    const float4* s = (const float4*)(x + (size_t)src * DMODEL);
    float4* d = (float4*)(g_xflip + (size_t)row * DMODEL);
    d[threadIdx.x] = s[threadIdx.x];
}

// ---------------- SGEMM: C[M,N] = A[M,K] @ W[N,K]^T (both K-major) ---------
#define BM 128
#define BN 128
#define BK 16

__global__ __launch_bounds__(256) void sgemm_nt(
    const float* __restrict__ A, const float* __restrict__ W,
    float* __restrict__ C, int M, int N, int K)
{
    __shared__ float As[BK][BM];
    __shared__ float Ws[BK][BN];
    int bm = blockIdx.y * BM;
    int bn = blockIdx.x * BN;
    int tid = threadIdx.x;
    int tx = tid & 15, ty = tid >> 4;

    float acc[8][8];
#pragma unroll
    for (int i = 0; i < 8; i++)
#pragma unroll
        for (int j = 0; j < 8; j++) acc[i][j] = 0.f;

    for (int k0 = 0; k0 < K; k0 += BK) {
#pragma unroll
        for (int i = 0; i < 2; i++) {
            int id = tid * 2 + i;            // 0..511
            int r  = id >> 2;                // 0..127
            int c4 = (id & 3) << 2;          // 0,4,8,12
            float4 v = *(const float4*)&A[(size_t)(bm + r) * K + k0 + c4];
            As[c4 + 0][r] = v.x; As[c4 + 1][r] = v.y;
            As[c4 + 2][r] = v.z; As[c4 + 3][r] = v.w;
        }
#pragma unroll
        for (int i = 0; i < 2; i++) {
            int id = tid * 2 + i;
            int r  = id >> 2;
            int c4 = (id & 3) << 2;
            int n  = bn + r;
            float4 v = make_float4(0.f, 0.f, 0.f, 0.f);
            if (n < N) v = *(const float4*)&W[(size_t)n * K + k0 + c4];
            Ws[c4 + 0][r] = v.x; Ws[c4 + 1][r] = v.y;
            Ws[c4 + 2][r] = v.z; Ws[c4 + 3][r] = v.w;
        }
        __syncthreads();
#pragma unroll
        for (int kk = 0; kk < BK; kk++) {
            float a[8], w[8];
            float4 a0 = *(const float4*)&As[kk][ty * 8];
            float4 a1 = *(const float4*)&As[kk][ty * 8 + 4];
            float4 w0 = *(const float4*)&Ws[kk][tx * 8];
            float4 w1 = *(const float4*)&Ws[kk][tx * 8 + 4];
            a[0]=a0.x; a[1]=a0.y; a[2]=a0.z; a[3]=a0.w;
            a[4]=a1.x; a[5]=a1.y; a[6]=a1.z; a[7]=a1.w;
            w[0]=w0.x; w[1]=w0.y; w[2]=w0.z; w[3]=w0.w;
            w[4]=w1.x; w[5]=w1.y; w[6]=w1.z; w[7]=w1.w;
#pragma unroll
            for (int i = 0; i < 8; i++)
#pragma unroll
                for (int j = 0; j < 8; j++)
                    acc[i][j] = fmaf(a[i], w[j], acc[i][j]);
        }
        __syncthreads();
    }

#pragma unroll
    for (int i = 0; i < 8; i++) {
        int m = bm + ty * 8 + i;
#pragma unroll
        for (int j = 0; j < 8; j++) {
            int n = bn + tx * 8 + j;
            if (n < N) C[(size_t)m * N + n] = acc[i][j];
        }
    }
}

// ---------------- depthwise causal conv (D_CONV=4) + bias + silu -----------
__global__ void conv_silu(const float* __restrict__ fw, const float* __restrict__ fb,
                          const float* __restrict__ bw, const float* __restrict__ bb) {
    int idx = blockIdx.x * blockDim.x + threadIdx.x;
    if (idx >= 2 * M_ROWS * CONVDIM) return;
    int c   = idx % CONVDIM;
    int r   = idx / CONVDIM;        // dir*2048 + row
    int dir = r >> 11;
    int row = r & 2047;
    int t   = row & 1023;
    const float* w    = dir ? bw : fw;
    const float* bias = dir ? bb : fb;
    const float* zx   = g_zx[dir];
    float acc = bias[c];
#pragma unroll
    for (int j = 0; j < 4; j++) {
        int tj = t - 3 + j;
        if (tj >= 0)
            acc = fmaf(w[j * CONVDIM + c],
                       zx[(size_t)(row - 3 + j) * DINPROJ + DINNER + c], acc);
    }
    float s = acc / (1.f + expf(-acc));     // silu
    g_xbc[dir][(size_t)row * CONVDIM + c] = s;
}

// ---------------- dt = softplus(dt_raw + bias), dA = exp(dt*A) -------------
__global__ void dt_kernel(const float* __restrict__ f_dtb, const float* __restrict__ f_alog,
                          const float* __restrict__ b_dtb, const float* __restrict__ b_alog) {
    int idx = blockIdx.x * blockDim.x + threadIdx.x;
    if (idx >= 2 * M_ROWS * NHEADS) return;
    int h   = idx & 31;
    int r   = idx >> 5;
    int dir = r >> 11;
    int row = r & 2047;
    const float* db = dir ? b_dtb : f_dtb;
    const float* al = dir ? b_alog : f_alog;
    float xr = g_zx[dir][(size_t)row * DINPROJ + (DINNER + CONVDIM) + h] + db[h];
    float dt = (xr > 20.f) ? xr : log1pf(expf(xr));
    float A  = -expf(al[h]);
    g_dt[dir][row * NHEADS + h] = dt;
    g_dA[dir][row * NHEADS + h] = expf(dt * A);
}

// ---------------- sequential SSM scan: one block per (dir,b,head) ----------
__global__ __launch_bounds__(256) void scan_kernel() {
    int blk = blockIdx.x;              // dir*64 + b*32 + h
    int dir = blk >> 6;
    int b   = (blk >> 5) & 1;
    int h   = blk & 31;
    int t   = threadIdx.x;
    int p   = t >> 2;                  // 0..63 head-dim index
    int ns  = (t & 3) << 4;            // 0,16,32,48 state slice

    float st[16];
#pragma unroll
    for (int i = 0; i < 16; i++) st[i] = 0.f;

    const float* xbc = g_xbc[dir] + (size_t)(b * L_SEQ) * CONVDIM;
    const float* dtb = g_dt[dir] + (size_t)(b * L_SEQ) * NHEADS + h;
    const float* dAb = g_dA[dir] + (size_t)(b * L_SEQ) * NHEADS + h;
    float* yout = g_y[dir] + (size_t)(b * L_SEQ) * DINNER + h * HEADDIM + p;
    int xoff = h * HEADDIM + p;

    for (int tau = 0; tau < L_SEQ; tau++) {
        const float* rowp = xbc + (size_t)tau * CONVDIM;
        float dAv = dAb[tau * NHEADS];
        float dtv = dtb[tau * NHEADS];
        float xv  = rowp[xoff];
        float4 B0 = *(const float4*)(rowp + DINNER + ns);
        float4 B1 = *(const float4*)(rowp + DINNER + ns + 4);
        float4 B2 = *(const float4*)(rowp + DINNER + ns + 8);
        float4 B3 = *(const float4*)(rowp + DINNER + ns + 12);
        float4 C0 = *(const float4*)(rowp + DINNER + DSTATE + ns);
        float4 C1 = *(const float4*)(rowp + DINNER + DSTATE + ns + 4);
        float4 C2 = *(const float4*)(rowp + DINNER + DSTATE + ns + 8);
        float4 C3 = *(const float4*)(rowp + DINNER + DSTATE + ns + 12);
        float coef = dtv * xv;
        float acc = 0.f;
        st[ 0] = fmaf(st[ 0], dAv, coef * B0.x); acc = fmaf(st[ 0], C0.x, acc);
        st[ 1] = fmaf(st[ 1], dAv, coef * B0.y); acc = fmaf(st[ 1], C0.y, acc);
        st[ 2] = fmaf(st[ 2], dAv, coef * B0.z); acc = fmaf(st[ 2], C0.z, acc);
        st[ 3] = fmaf(st[ 3], dAv, coef * B0.w); acc = fmaf(st[ 3], C0.w, acc);
        st[ 4] = fmaf(st[ 4], dAv, coef * B1.x); acc = fmaf(st[ 4], C1.x, acc);
        st[ 5] = fmaf(st[ 5], dAv, coef * B1.y); acc = fmaf(st[ 5], C1.y, acc);
        st[ 6] = fmaf(st[ 6], dAv, coef * B1.z); acc = fmaf(st[ 6], C1.z, acc);
        st[ 7] = fmaf(st[ 7], dAv, coef * B1.w); acc = fmaf(st[ 7], C1.w, acc);
        st[ 8] = fmaf(st[ 8], dAv, coef * B2.x); acc = fmaf(st[ 8], C2.x, acc);
        st[ 9] = fmaf(st[ 9], dAv, coef * B2.y); acc = fmaf(st[ 9], C2.y, acc);
        st[10] = fmaf(st[10], dAv, coef * B2.z); acc = fmaf(st[10], C2.z, acc);
        st[11] = fmaf(st[11], dAv, coef * B2.w); acc = fmaf(st[11], C2.w, acc);
        st[12] = fmaf(st[12], dAv, coef * B3.x); acc = fmaf(st[12], C3.x, acc);
        st[13] = fmaf(st[13], dAv, coef * B3.y); acc = fmaf(st[13], C3.y, acc);
        st[14] = fmaf(st[14], dAv, coef * B3.z); acc = fmaf(st[14], C3.z, acc);
        st[15] = fmaf(st[15], dAv, coef * B3.w); acc = fmaf(st[15], C3.w, acc);
        acc += __shfl_xor_sync(0xffffffffu, acc, 1);
        acc += __shfl_xor_sync(0xffffffffu, acc, 2);
        if ((t & 3) == 0) yout[(size_t)tau * DINNER] = acc;
    }
}

// ---------------- y = (scan + D*x) * silu(z); gated RMSNorm ----------------
__global__ __launch_bounds__(256) void gate_rms(const float* __restrict__ fD, const float* __restrict__ frms,
                                                const float* __restrict__ bD, const float* __restrict__ brms) {
    int blk = blockIdx.x;            // dir*2048 + row
    int dir = blk >> 11;
    int row = blk & 2047;
    const float* Dp = dir ? bD : fD;
    const float* rw = dir ? brms : frms;
    const float* zrow = g_zx[dir] + (size_t)row * DINPROJ;
    const float* xrow = g_xbc[dir] + (size_t)row * CONVDIM;
    float* yrow = g_y[dir] + (size_t)row * DINNER;

    float vals[8];
    float ss = 0.f;
#pragma unroll
    for (int i = 0; i < 8; i++) {
        int c = threadIdx.x + (i << 8);
        float y = fmaf(Dp[c >> 6], xrow[c], yrow[c]);
        float z = zrow[c];
        y *= z / (1.f + expf(-z));
        vals[i] = y;
        ss = fmaf(y, y, ss);
    }
    __shared__ float red[8];
    __shared__ float s_scale;
#pragma unroll
    for (int o = 16; o; o >>= 1) ss += __shfl_xor_sync(0xffffffffu, ss, o);
    if ((threadIdx.x & 31) == 0) red[threadIdx.x >> 5] = ss;
    __syncthreads();
    if (threadIdx.x == 0) {
        float tot = 0.f;
#pragma unroll
        for (int i = 0; i < 8; i++) tot += red[i];
        s_scale = rsqrtf(tot / (float)DINNER + 1e-5f);
    }
    __syncthreads();
    float sc = s_scale;
#pragma unroll
    for (int i = 0; i < 8; i++) {
        int c = threadIdx.x + (i << 8);
        yrow[c] = vals[i] * sc * rw[c];
    }
}

// ---------------- concat(fwd, flip(bwd)) into (2048, 2048) -----------------
__global__ void concat_kernel() {
    int idx = blockIdx.x * blockDim.x + threadIdx.x;   // float4 index
    int r  = idx >> 9;                 // row (original time)
    int c4 = (idx & 511) << 2;         // 0..2044
    float4 v;
    if (c4 < DMODEL) {
        v = *(const float4*)(g_dirout[0] + (size_t)r * DMODEL + c4);
    } else {
        int b = r >> 10, t = r & 1023;
        int lr = (b << 10) + (1023 - t);
        v = *(const float4*)(g_dirout[1] + (size_t)lr * DMODEL + (c4 - DMODEL));
    }
    *(float4*)(g_cat + (size_t)r * DINNER + c4) = v;
}

// ---------------- residual + bias + LayerNorm -> d_out ---------------------
__global__ __launch_bounds__(256) void ln_kernel(const float* __restrict__ x,
        const float* __restrict__ pb, const float* __restrict__ lw,
        const float* __restrict__ lb, float* __restrict__ out) {
    int row = blockIdx.x;
    const float* hr = g_hbuf + (size_t)row * DMODEL;
    const float* xr = x + (size_t)row * DMODEL;
    float v[4];
    float sum = 0.f;
#pragma unroll
    for (int i = 0; i < 4; i++) {
        int c = threadIdx.x + (i << 8);
        v[i] = hr[c] + xr[c] + pb[c];
        sum += v[i];
    }
    __shared__ float red[8];
    __shared__ float s_mu, s_inv;
#pragma unroll
    for (int o = 16; o; o >>= 1) sum += __shfl_xor_sync(0xffffffffu, sum, o);
    if ((threadIdx.x & 31) == 0) red[threadIdx.x >> 5] = sum;
    __syncthreads();
    if (threadIdx.x == 0) {
        float tot = 0.f;
#pragma unroll
        for (int i = 0; i < 8; i++) tot += red[i];
        s_mu = tot / (float)DMODEL;
    }
    __syncthreads();
    float mu = s_mu;
    float vs = 0.f;
#pragma unroll
    for (int i = 0; i < 4; i++) { float d = v[i] - mu; vs = fmaf(d, d, vs); }
#pragma unroll
    for (int o = 16; o; o >>= 1) vs += __shfl_xor_sync(0xffffffffu, vs, o);
    if ((threadIdx.x & 31) == 0) red[threadIdx.x >> 5] = vs;
    __syncthreads();
    if (threadIdx.x == 0) {
        float tot = 0.f;
#pragma unroll
        for (int i = 0; i < 8; i++) tot += red[i];
        s_inv = rsqrtf(tot / (float)DMODEL + 1e-5f);
    }
    __syncthreads();
    float inv = s_inv;
#pragma unroll
    for (int i = 0; i < 4; i++) {
        int c = threadIdx.x + (i << 8);
        out[(size_t)row * DMODEL + c] = (v[i] - mu) * inv * lw[c] + lb[c];
    }
}

// ---------------- host orchestration ---------------------------------------
extern "C" void kernel_launch(void* const* d_in, const int* in_sizes, int n_in,
                              void* d_out, int out_size) {
    const float* x            = (const float*)d_in[0];
    const float* f_in_proj_w  = (const float*)d_in[1];
    const float* f_conv_w     = (const float*)d_in[2];
    const float* f_conv_b     = (const float*)d_in[3];
    const float* f_dt_bias    = (const float*)d_in[4];
    const float* f_A_log      = (const float*)d_in[5];
    const float* f_D          = (const float*)d_in[6];
    const float* f_rms_w      = (const float*)d_in[7];
    const float* f_out_proj_w = (const float*)d_in[8];
    const float* b_in_proj_w  = (const float*)d_in[9];
    const float* b_conv_w     = (const float*)d_in[10];
    const float* b_conv_b     = (const float*)d_in[11];
    const float* b_dt_bias    = (const float*)d_in[12];
    const float* b_A_log      = (const float*)d_in[13];
    const float* b_D          = (const float*)d_in[14];
    const float* b_rms_w      = (const float*)d_in[15];
    const float* b_out_proj_w = (const float*)d_in[16];
    const float* proj_w       = (const float*)d_in[17];
    const float* proj_b       = (const float*)d_in[18];
    const float* ln_w         = (const float*)d_in[19];
    const float* ln_b         = (const float*)d_in[20];
    float* out = (float*)d_out;

    float *p_xflip, *p_zx, *p_xbc, *p_y, *p_dirout, *p_cat, *p_hbuf;
    cudaGetSymbolAddress((void**)&p_xflip,  g_xflip);
    cudaGetSymbolAddress((void**)&p_zx,     g_zx);
    cudaGetSymbolAddress((void**)&p_xbc,    g_xbc);
    cudaGetSymbolAddress((void**)&p_y,      g_y);
    cudaGetSymbolAddress((void**)&p_dirout, g_dirout);
    cudaGetSymbolAddress((void**)&p_cat,    g_cat);
    cudaGetSymbolAddress((void**)&p_hbuf,   g_hbuf);

    // 1) flipped copy of x for the backward direction
    flip_copy<<<M_ROWS, 256>>>(x);

    // 2) in_proj GEMMs (local time): (2048,1024) @ (4256,1024)^T
    {
        dim3 grid((DINPROJ + BN - 1) / BN, M_ROWS / BM);
        sgemm_nt<<<grid, 256>>>(x,       f_in_proj_w, p_zx,                      M_ROWS, DINPROJ, DMODEL);
        sgemm_nt<<<grid, 256>>>(p_xflip, b_in_proj_w, p_zx + (size_t)M_ROWS * DINPROJ, M_ROWS, DINPROJ, DMODEL);
    }

    // 3) depthwise conv + silu; dt/dA
    conv_silu<<<(2 * M_ROWS * CONVDIM + 255) / 256, 256>>>(f_conv_w, f_conv_b, b_conv_w, b_conv_b);
    dt_kernel<<<(2 * M_ROWS * NHEADS + 255) / 256, 256>>>(f_dt_bias, f_A_log, b_dt_bias, b_A_log);

    // 4) sequential SSM scan
    scan_kernel<<<128, 256>>>();

    // 5) gating + RMSNorm
    gate_rms<<<2 * M_ROWS, 256>>>(f_D, f_rms_w, b_D, b_rms_w);

    // 6) out_proj GEMMs per direction
    {
        dim3 grid(DMODEL / BN, M_ROWS / BM);
        sgemm_nt<<<grid, 256>>>(p_y,                             f_out_proj_w, p_dirout,                            M_ROWS, DMODEL, DINNER);
        sgemm_nt<<<grid, 256>>>(p_y + (size_t)M_ROWS * DINNER,   b_out_proj_w, p_dirout + (size_t)M_ROWS * DMODEL,  M_ROWS, DMODEL, DINNER);
    }

    // 7) concat (un-flip bwd) + final projection
    concat_kernel<<<(M_ROWS * DINNER / 4 + 255) / 256, 256>>>();
    {
        dim3 grid(DMODEL / BN, M_ROWS / BM);
        sgemm_nt<<<grid, 256>>>(p_cat, proj_w, p_hbuf, M_ROWS, DMODEL, DINNER);
    }

    // 8) residual + bias + LayerNorm
    ln_kernel<<<M_ROWS, 256>>>(x, proj_b, ln_w, ln_b, out);
}

// round 3
// speedup vs baseline: 2.0907x; 2.0907x over previous
#include <cuda_runtime.h>
#include <cuda_fp16.h>
#include <math.h>
#include <stdint.h>

#define L_SEQ   1024
#define BATCH   2
#define DMODEL  1024
#define DINNER  2048
#define NHEADS  32
#define HEADDIM 64
#define DSTATE  64
#define CONVDIM 2176
#define DINPROJ 4256
#define DINPROJ_PAD 4352
#define M_ROWS  2048   // BATCH * L_SEQ

// ===================== scratch (device globals) =============================
__device__ float g_zx[2][M_ROWS * DINPROJ];
__device__ float g_xbc[2][M_ROWS * CONVDIM];
__device__ float g_dt[2][M_ROWS * NHEADS];
__device__ float g_dA[2][M_ROWS * NHEADS];
__device__ float g_y[2][M_ROWS * DINNER];
__device__ float g_dirout[2][M_ROWS * DMODEL];
__device__ float g_hbuf[M_ROWS * DMODEL];

__device__ __half g_xh[2][M_ROWS * DMODEL];          // dir0 = x, dir1 = flip(x)
__device__ __half g_wip_h[2][DINPROJ_PAD * DMODEL];  // in_proj weights (padded rows)
__device__ __half g_yh[2][M_ROWS * DINNER];          // gated/normed y
__device__ __half g_woh[2][DMODEL * DINNER];         // out_proj weights
__device__ __half g_cath[M_ROWS * DINNER];           // concat(fwd, flip(bwd))
__device__ __half g_wprh[DMODEL * DINNER];           // final proj weights

// ===================== fp32 -> fp16 converts =================================
__global__ void cvt_x_kernel(const float* __restrict__ x) {
    int idx = blockIdx.x * blockDim.x + threadIdx.x;
    if (idx >= M_ROWS * DMODEL) return;
    int row = idx >> 10, c = idx & 1023;
    __half v = __float2half_rn(x[idx]);
    g_xh[0][idx] = v;
    int b = row >> 10, t = row & 1023;
    g_xh[1][(((b << 10) + (1023 - t)) << 10) + c] = v;
}

__global__ void cvt_w_kernel(const float* __restrict__ w, __half* __restrict__ dst,
                             int nsrc, int ntot) {
    int idx = blockIdx.x * blockDim.x + threadIdx.x;
    if (idx >= ntot) return;
    dst[idx] = __float2half_rn(idx < nsrc ? w[idx] : 0.f);
}

// ===================== HMMA fp16 GEMM: C[M,N] = A[M,K] @ B[N,K]^T ===========
// CTA tile 128x128, K-tile 64, 3-stage cp.async pipeline, 8 warps (32x64 each)
#define KT 64
#define RS 72                    // row stride in halves (64 + 8 pad = 144 B)
#define A_ST_BYTES (128 * RS * 2)     // 18432
#define ST_BYTES   (2 * A_ST_BYTES)   // 36864 per stage
#define G_SMEM     (3 * ST_BYTES)     // 110592

__device__ __forceinline__ uint32_t smem_u32(const void* p) {
    uint32_t a;
    asm("{ .reg .u64 t; cvta.to.shared.u64 t, %1; cvt.u32.u64 %0, t; }" : "=r"(a) : "l"(p));
    return a;
}
__device__ __forceinline__ void cp_async16(uint32_t s, const void* g) {
    asm volatile("cp.async.cg.shared.global [%0], [%1], 16;" :: "r"(s), "l"(g));
}
__device__ __forceinline__ void cp_commit() { asm volatile("cp.async.commit_group;" ::: "memory"); }
__device__ __forceinline__ void cp_wait1()  { asm volatile("cp.async.wait_group 1;" ::: "memory"); }
__device__ __forceinline__ void ldmatrix4(uint32_t& r0, uint32_t& r1, uint32_t& r2, uint32_t& r3, uint32_t a) {
    asm volatile("ldmatrix.sync.aligned.m8n8.x4.shared.b16 {%0,%1,%2,%3}, [%4];"
                 : "=r"(r0), "=r"(r1), "=r"(r2), "=r"(r3) : "r"(a));
}
__device__ __forceinline__ void mma16816(float* c, const uint32_t* a, const uint32_t* b) {
    asm volatile("mma.sync.aligned.m16n8k16.row.col.f32.f16.f16.f32 "
                 "{%0,%1,%2,%3}, {%4,%5,%6,%7}, {%8,%9}, {%0,%1,%2,%3};"
                 : "+f"(c[0]), "+f"(c[1]), "+f"(c[2]), "+f"(c[3])
                 : "r"(a[0]), "r"(a[1]), "r"(a[2]), "r"(a[3]), "r"(b[0]), "r"(b[1]));
}

__global__ __launch_bounds__(256, 1) void gemm_hmma(
    const __half* __restrict__ A, const __half* __restrict__ B,
    float* __restrict__ C, int K, int Nreal, int ldc)
{
    extern __shared__ char smem[];
    const uint32_t sb = smem_u32(smem);
    const int tid = threadIdx.x;
    const int lane = tid & 31;
    const int warp = tid >> 5;
    const int bm = blockIdx.y * 128;
    const int bn = blockIdx.x * 128;
    const int wm = (warp & 3) * 32;
    const int wn = (warp >> 2) * 64;

    const int T = K / KT;

    // cp.async thread mapping (reused per stage): 1024 16B chunks per matrix
    // chunk id = tid + 256*it ; r = id>>3 (row), ck = id&7 (16B chunk in row)
    auto load_stage = [&](int t, int s) {
        const uint32_t so = sb + (uint32_t)s * ST_BYTES;
        const int k0 = t * KT;
#pragma unroll
        for (int it = 0; it < 4; it++) {
            int id = tid + (it << 8);
            int r = id >> 3, ck = id & 7;
            uint32_t sm = so + r * (RS * 2) + ck * 16;
            cp_async16(sm, A + (size_t)(bm + r) * K + k0 + ck * 8);
            cp_async16(sm + A_ST_BYTES, B + (size_t)(bn + r) * K + k0 + ck * 8);
        }
    };

    float acc[2][8][4];
#pragma unroll
    for (int i = 0; i < 2; i++)
#pragma unroll
        for (int j = 0; j < 8; j++)
#pragma unroll
            for (int q = 0; q < 4; q++) acc[i][j][q] = 0.f;

    load_stage(0, 0); cp_commit();
    load_stage(1, 1); cp_commit();

    // per-thread ldmatrix base offsets (bytes, within stage)
    uint32_t a_off[2], b_off[4];
#pragma unroll
    for (int mi = 0; mi < 2; mi++)
        a_off[mi] = (wm + mi * 16 + (lane & 15)) * (RS * 2) + ((lane >> 4) << 4);
#pragma unroll
    for (int nj = 0; nj < 4; nj++)
        b_off[nj] = (uint32_t)(wn + nj * 16 + (lane & 7) + ((lane >> 4) << 3)) * (RS * 2)
                  + (((lane >> 3) & 1) << 4) + A_ST_BYTES;

    for (int t = 0; t < T; t++) {
        cp_wait1();
        __syncthreads();
        if (t + 2 < T) load_stage(t + 2, (t + 2) % 3);
        cp_commit();

        const uint32_t so = sb + (uint32_t)(t % 3) * ST_BYTES;
#pragma unroll
        for (int k16 = 0; k16 < 4; k16++) {
            uint32_t afr[2][4];
#pragma unroll
            for (int mi = 0; mi < 2; mi++)
                ldmatrix4(afr[mi][0], afr[mi][1], afr[mi][2], afr[mi][3],
                          so + a_off[mi] + k16 * 32);
            uint32_t bfr[8][2];
#pragma unroll
            for (int nj = 0; nj < 4; nj++) {
                uint32_t r0, r1, r2, r3;
                ldmatrix4(r0, r1, r2, r3, so + b_off[nj] + k16 * 32);
                bfr[2 * nj][0] = r0; bfr[2 * nj][1] = r1;
                bfr[2 * nj + 1][0] = r2; bfr[2 * nj + 1][1] = r3;
            }
#pragma unroll
            for (int mi = 0; mi < 2; mi++)
#pragma unroll
                for (int ni = 0; ni < 8; ni++)
                    mma16816(acc[mi][ni], afr[mi], bfr[ni]);
        }
        __syncthreads();
    }

    // epilogue
#pragma unroll
    for (int mi = 0; mi < 2; mi++) {
        int row = bm + wm + mi * 16 + (lane >> 2);
#pragma unroll
        for (int ni = 0; ni < 8; ni++) {
            int col = bn + wn + ni * 8 + ((lane & 3) << 1);
            if (col < Nreal) {
                *(float2*)&C[(size_t)row * ldc + col] = make_float2(acc[mi][ni][0], acc[mi][ni][1]);
                *(float2*)&C[(size_t)(row + 8) * ldc + col] = make_float2(acc[mi][ni][2], acc[mi][ni][3]);
            }
        }
    }
}

// ===================== fp32 recompute of dt columns =========================
// g_zx[dir][row, 4224+h] = dot(x_dir_row, w[4224+h]) in fp32 (h = 0..31)
__global__ __launch_bounds__(256) void fix_dt_kernel(const float* __restrict__ x,
        const float* __restrict__ fw, const float* __restrict__ bw) {
    __shared__ float xs[DMODEL];
    int blk = blockIdx.x;              // dir*2048 + row
    int dir = blk >> 11;
    int row = blk & 2047;
    int b = row >> 10, t = row & 1023;
    int srow = dir ? ((b << 10) + (1023 - t)) : row;
    const float* xr = x + (size_t)srow * DMODEL;
#pragma unroll
    for (int j = 0; j < 4; j++) xs[threadIdx.x + (j << 8)] = xr[threadIdx.x + (j << 8)];
    __syncthreads();
    int warp = threadIdx.x >> 5, lane = threadIdx.x & 31;
    const float* w = dir ? bw : fw;
#pragma unroll
    for (int hh = 0; hh < 4; hh++) {
        int h = warp * 4 + hh;
        const float* wr = w + (size_t)(DINNER + CONVDIM + h) * DMODEL;
        float s = 0.f;
#pragma unroll
        for (int j = 0; j < 32; j++) {
            int i = lane + (j << 5);
            s = fmaf(xs[i], wr[i], s);
        }
#pragma unroll
        for (int o = 16; o; o >>= 1) s += __shfl_xor_sync(0xffffffffu, s, o);
        if (lane == 0) g_zx[dir][(size_t)row * DINPROJ + (DINNER + CONVDIM) + h] = s;
    }
}

// ===================== depthwise conv + silu ================================
__global__ void conv_silu(const float* __restrict__ fw, const float* __restrict__ fb,
                          const float* __restrict__ bw, const float* __restrict__ bb) {
    int idx = blockIdx.x * blockDim.x + threadIdx.x;
    if (idx >= 2 * M_ROWS * CONVDIM) return;
    int c = idx % CONVDIM;
    int r = idx / CONVDIM;
    int dir = r >> 11;
    int row = r & 2047;
    int t = row & 1023;
    const float* w = dir ? bw : fw;
    const float* bias = dir ? bb : fb;
    const float* zx = g_zx[dir];
    float acc = bias[c];
#pragma unroll
    for (int j = 0; j < 4; j++) {
        int tj = t - 3 + j;
        if (tj >= 0)
            acc = fmaf(w[j * CONVDIM + c], zx[(size_t)(row - 3 + j) * DINPROJ + DINNER + c], acc);
    }
    g_xbc[dir][(size_t)row * CONVDIM + c] = acc / (1.f + expf(-acc));
}

// ===================== dt / dA =============================================
__global__ void dt_kernel(const float* __restrict__ f_dtb, const float* __restrict__ f_alog,
                          const float* __restrict__ b_dtb, const float* __restrict__ b_alog) {
    int idx = blockIdx.x * blockDim.x + threadIdx.x;
    if (idx >= 2 * M_ROWS * NHEADS) return;
    int h = idx & 31;
    int r = idx >> 5;
    int dir = r >> 11;
    int row = r & 2047;
    const float* db = dir ? b_dtb : f_dtb;
    const float* al = dir ? b_alog : f_alog;
    float xr = g_zx[dir][(size_t)row * DINPROJ + (DINNER + CONVDIM) + h] + db[h];
    float dt = (xr > 20.f) ? xr : log1pf(expf(xr));
    float A = -expf(al[h]);
    g_dt[dir][row * NHEADS + h] = dt;
    g_dA[dir][row * NHEADS + h] = expf(dt * A);
}

// ===================== SSM scan =============================================
__global__ __launch_bounds__(256) void scan_kernel() {
    int blk = blockIdx.x;
    int dir = blk >> 6;
    int b = (blk >> 5) & 1;
    int h = blk & 31;
    int t = threadIdx.x;
    int p = t >> 2;
    int ns = (t & 3) << 4;

    float st[16];
#pragma unroll
    for (int i = 0; i < 16; i++) st[i] = 0.f;

    const float* xbc = g_xbc[dir] + (size_t)(b * L_SEQ) * CONVDIM;
    const float* dtb = g_dt[dir] + (size_t)(b * L_SEQ) * NHEADS + h;
    const float* dAb = g_dA[dir] + (size_t)(b * L_SEQ) * NHEADS + h;
    float* yout = g_y[dir] + (size_t)(b * L_SEQ) * DINNER + h * HEADDIM + p;
    int xoff = h * HEADDIM + p;

    for (int tau = 0; tau < L_SEQ; tau++) {
        const float* rowp = xbc + (size_t)tau * CONVDIM;
        float dAv = dAb[tau * NHEADS];
        float dtv = dtb[tau * NHEADS];
        float xv = rowp[xoff];
        float4 B0 = *(const float4*)(rowp + DINNER + ns);
        float4 B1 = *(const float4*)(rowp + DINNER + ns + 4);
        float4 B2 = *(const float4*)(rowp + DINNER + ns + 8);
        float4 B3 = *(const float4*)(rowp + DINNER + ns + 12);
        float4 C0 = *(const float4*)(rowp + DINNER + DSTATE + ns);
        float4 C1 = *(const float4*)(rowp + DINNER + DSTATE + ns + 4);
        float4 C2 = *(const float4*)(rowp + DINNER + DSTATE + ns + 8);
        float4 C3 = *(const float4*)(rowp + DINNER + DSTATE + ns + 12);
        float coef = dtv * xv;
        float acc = 0.f;
        st[ 0] = fmaf(st[ 0], dAv, coef * B0.x); acc = fmaf(st[ 0], C0.x, acc);
        st[ 1] = fmaf(st[ 1], dAv, coef * B0.y); acc = fmaf(st[ 1], C0.y, acc);
        st[ 2] = fmaf(st[ 2], dAv, coef * B0.z); acc = fmaf(st[ 2], C0.z, acc);
        st[ 3] = fmaf(st[ 3], dAv, coef * B0.w); acc = fmaf(st[ 3], C0.w, acc);
        st[ 4] = fmaf(st[ 4], dAv, coef * B1.x); acc = fmaf(st[ 4], C1.x, acc);
        st[ 5] = fmaf(st[ 5], dAv, coef * B1.y); acc = fmaf(st[ 5], C1.y, acc);
        st[ 6] = fmaf(st[ 6], dAv, coef * B1.z); acc = fmaf(st[ 6], C1.z, acc);
        st[ 7] = fmaf(st[ 7], dAv, coef * B1.w); acc = fmaf(st[ 7], C1.w, acc);
        st[ 8] = fmaf(st[ 8], dAv, coef * B2.x); acc = fmaf(st[ 8], C2.x, acc);
        st[ 9] = fmaf(st[ 9], dAv, coef * B2.y); acc = fmaf(st[ 9], C2.y, acc);
        st[10] = fmaf(st[10], dAv, coef * B2.z); acc = fmaf(st[10], C2.z, acc);
        st[11] = fmaf(st[11], dAv, coef * B2.w); acc = fmaf(st[11], C2.w, acc);
        st[12] = fmaf(st[12], dAv, coef * B3.x); acc = fmaf(st[12], C3.x, acc);
        st[13] = fmaf(st[13], dAv, coef * B3.y); acc = fmaf(st[13], C3.y, acc);
        st[14] = fmaf(st[14], dAv, coef * B3.z); acc = fmaf(st[14], C3.z, acc);
        st[15] = fmaf(st[15], dAv, coef * B3.w); acc = fmaf(st[15], C3.w, acc);
        acc += __shfl_xor_sync(0xffffffffu, acc, 1);
        acc += __shfl_xor_sync(0xffffffffu, acc, 2);
        if ((t & 3) == 0) yout[(size_t)tau * DINNER] = acc;
    }
}

// ===================== gate + RMSNorm -> fp16 ===============================
__global__ __launch_bounds__(256) void gate_rms(const float* __restrict__ fD, const float* __restrict__ frms,
                                                const float* __restrict__ bD, const float* __restrict__ brms) {
    int blk = blockIdx.x;
    int dir = blk >> 11;
    int row = blk & 2047;
    const float* Dp = dir ? bD : fD;
    const float* rw = dir ? brms : frms;
    const float* zrow = g_zx[dir] + (size_t)row * DINPROJ;
    const float* xrow = g_xbc[dir] + (size_t)row * CONVDIM;
    const float* yrow = g_y[dir] + (size_t)row * DINNER;

    float vals[8];
    float ss = 0.f;
#pragma unroll
    for (int i = 0; i < 8; i++) {
        int c = threadIdx.x + (i << 8);
        float y = fmaf(Dp[c >> 6], xrow[c], yrow[c]);
        float z = zrow[c];
        y *= z / (1.f + expf(-z));
        vals[i] = y;
        ss = fmaf(y, y, ss);
    }
    __shared__ float red[8];
    __shared__ float s_scale;
#pragma unroll
    for (int o = 16; o; o >>= 1) ss += __shfl_xor_sync(0xffffffffu, ss, o);
    if ((threadIdx.x & 31) == 0) red[threadIdx.x >> 5] = ss;
    __syncthreads();
    if (threadIdx.x == 0) {
        float tot = 0.f;
#pragma unroll
        for (int i = 0; i < 8; i++) tot += red[i];
        s_scale = rsqrtf(tot / (float)DINNER + 1e-5f);
    }
    __syncthreads();
    float sc = s_scale;
#pragma unroll
    for (int i = 0; i < 8; i++) {
        int c = threadIdx.x + (i << 8);
        g_yh[dir][(size_t)row * DINNER + c] = __float2half_rn(vals[i] * sc * rw[c]);
    }
}

// ===================== concat (un-flip bwd) -> fp16 =========================
__global__ void concat_h() {
    int idx = blockIdx.x * blockDim.x + threadIdx.x;
    if (idx >= M_ROWS * DINNER) return;
    int r = idx >> 11;
    int c = idx & 2047;
    float v;
    if (c < DMODEL) {
        v = g_dirout[0][(size_t)r * DMODEL + c];
    } else {
        int b = r >> 10, t = r & 1023;
        int lr = (b << 10) + (1023 - t);
        v = g_dirout[1][(size_t)lr * DMODEL + (c - DMODEL)];
    }
    g_cath[idx] = __float2half_rn(v);
}

// ===================== residual + LayerNorm ================================
__global__ __launch_bounds__(256) void ln_kernel(const float* __restrict__ x,
        const float* __restrict__ pb, const float* __restrict__ lw,
        const float* __restrict__ lb, float* __restrict__ out) {
    int row = blockIdx.x;
    const float* hr = g_hbuf + (size_t)row * DMODEL;
    const float* xr = x + (size_t)row * DMODEL;
    float v[4];
    float sum = 0.f;
#pragma unroll
    for (int i = 0; i < 4; i++) {
        int c = threadIdx.x + (i << 8);
        v[i] = hr[c] + xr[c] + pb[c];
        sum += v[i];
    }
    __shared__ float red[8];
    __shared__ float s_mu, s_inv;
#pragma unroll
    for (int o = 16; o; o >>= 1) sum += __shfl_xor_sync(0xffffffffu, sum, o);
    if ((threadIdx.x & 31) == 0) red[threadIdx.x >> 5] = sum;
    __syncthreads();
    if (threadIdx.x == 0) {
        float tot = 0.f;
#pragma unroll
        for (int i = 0; i < 8; i++) tot += red[i];
        s_mu = tot / (float)DMODEL;
    }
    __syncthreads();
    float mu = s_mu;
    float vs = 0.f;
#pragma unroll
    for (int i = 0; i < 4; i++) { float d = v[i] - mu; vs = fmaf(d, d, vs); }
#pragma unroll
    for (int o = 16; o; o >>= 1) vs += __shfl_xor_sync(0xffffffffu, vs, o);
    if ((threadIdx.x & 31) == 0) red[threadIdx.x >> 5] = vs;
    __syncthreads();
    if (threadIdx.x == 0) {
        float tot = 0.f;
#pragma unroll
        for (int i = 0; i < 8; i++) tot += red[i];
        s_inv = rsqrtf(tot / (float)DMODEL + 1e-5f);
    }
    __syncthreads();
    float inv = s_inv;
#pragma unroll
    for (int i = 0; i < 4; i++) {
        int c = threadIdx.x + (i << 8);
        out[(size_t)row * DMODEL + c] = (v[i] - mu) * inv * lw[c] + lb[c];
    }
}

// ===================== host orchestration ===================================
extern "C" void kernel_launch(void* const* d_in, const int* in_sizes, int n_in,
                              void* d_out, int out_size) {
    const float* x            = (const float*)d_in[0];
    const float* f_in_proj_w  = (const float*)d_in[1];
    const float* f_conv_w     = (const float*)d_in[2];
    const float* f_conv_b     = (const float*)d_in[3];
    const float* f_dt_bias    = (const float*)d_in[4];
    const float* f_A_log      = (const float*)d_in[5];
    const float* f_D          = (const float*)d_in[6];
    const float* f_rms_w      = (const float*)d_in[7];
    const float* f_out_proj_w = (const float*)d_in[8];
    const float* b_in_proj_w  = (const float*)d_in[9];
    const float* b_conv_w     = (const float*)d_in[10];
    const float* b_conv_b     = (const float*)d_in[11];
    const float* b_dt_bias    = (const float*)d_in[12];
    const float* b_A_log      = (const float*)d_in[13];
    const float* b_D          = (const float*)d_in[14];
    const float* b_rms_w      = (const float*)d_in[15];
    const float* b_out_proj_w = (const float*)d_in[16];
    const float* proj_w       = (const float*)d_in[17];
    const float* proj_b       = (const float*)d_in[18];
    const float* ln_w         = (const float*)d_in[19];
    const float* ln_b         = (const float*)d_in[20];
    float* out = (float*)d_out;

    float *p_zx, *p_dirout, *p_hbuf;
    __half *p_xh, *p_wip, *p_yh, *p_woh, *p_cath, *p_wprh;
    cudaGetSymbolAddress((void**)&p_zx, g_zx);
    cudaGetSymbolAddress((void**)&p_dirout, g_dirout);
    cudaGetSymbolAddress((void**)&p_hbuf, g_hbuf);
    cudaGetSymbolAddress((void**)&p_xh, g_xh);
    cudaGetSymbolAddress((void**)&p_wip, g_wip_h);
    cudaGetSymbolAddress((void**)&p_yh, g_yh);
    cudaGetSymbolAddress((void**)&p_woh, g_woh);
    cudaGetSymbolAddress((void**)&p_cath, g_cath);
    cudaGetSymbolAddress((void**)&p_wprh, g_wprh);

    cudaFuncSetAttribute(gemm_hmma, cudaFuncAttributeMaxDynamicSharedMemorySize, G_SMEM);

    const size_t XSZ  = (size_t)M_ROWS * DMODEL;
    const size_t WIPS = (size_t)DINPROJ_PAD * DMODEL;
    const size_t YSZ  = (size_t)M_ROWS * DINNER;
    const size_t WOS  = (size_t)DMODEL * DINNER;

    // 0) converts
    cvt_x_kernel<<<(int)((XSZ + 255) / 256), 256>>>(x);
    cvt_w_kernel<<<(int)((WIPS + 255) / 256), 256>>>(f_in_proj_w, p_wip,        DINPROJ * DMODEL, (int)WIPS);
    cvt_w_kernel<<<(int)((WIPS + 255) / 256), 256>>>(b_in_proj_w, p_wip + WIPS, DINPROJ * DMODEL, (int)WIPS);
    cvt_w_kernel<<<(int)((WOS + 255) / 256), 256>>>(f_out_proj_w, p_woh,        (int)WOS, (int)WOS);
    cvt_w_kernel<<<(int)((WOS + 255) / 256), 256>>>(b_out_proj_w, p_woh + WOS,  (int)WOS, (int)WOS);
    cvt_w_kernel<<<(int)((WOS + 255) / 256), 256>>>(proj_w,       p_wprh,       (int)WOS, (int)WOS);

    // 1) in_proj GEMMs (fp16 HMMA): (2048,1024) @ (4256p4352,1024)^T
    {
        dim3 grid(DINPROJ_PAD / 128, M_ROWS / 128);
        gemm_hmma<<<grid, 256, G_SMEM>>>(p_xh,       p_wip,        p_zx,                           DMODEL, DINPROJ, DINPROJ);
        gemm_hmma<<<grid, 256, G_SMEM>>>(p_xh + XSZ, p_wip + WIPS, p_zx + (size_t)M_ROWS * DINPROJ, DMODEL, DINPROJ, DINPROJ);
    }

    // 1b) fp32 recompute of dt columns (exp-compounding path needs precision)
    fix_dt_kernel<<<2 * M_ROWS, 256>>>(x, f_in_proj_w, b_in_proj_w);

    // 2) conv + silu; dt / dA
    conv_silu<<<(2 * M_ROWS * CONVDIM + 255) / 256, 256>>>(f_conv_w, f_conv_b, b_conv_w, b_conv_b);
    dt_kernel<<<(2 * M_ROWS * NHEADS + 255) / 256, 256>>>(f_dt_bias, f_A_log, b_dt_bias, b_A_log);

    // 3) scan
    scan_kernel<<<128, 256>>>();

    // 4) gate + rmsnorm -> fp16
    gate_rms<<<2 * M_ROWS, 256>>>(f_D, f_rms_w, b_D, b_rms_w);

    // 5) out_proj GEMMs
    {
        dim3 grid(DMODEL / 128, M_ROWS / 128);
        gemm_hmma<<<grid, 256, G_SMEM>>>(p_yh,       p_woh,       p_dirout,                          DINNER, DMODEL, DMODEL);
        gemm_hmma<<<grid, 256, G_SMEM>>>(p_yh + YSZ, p_woh + WOS, p_dirout + (size_t)M_ROWS * DMODEL, DINNER, DMODEL, DMODEL);
    }

    // 6) concat + final proj GEMM
    concat_h<<<(M_ROWS * DINNER + 255) / 256, 256>>>();
    {
        dim3 grid(DMODEL / 128, M_ROWS / 128);
        gemm_hmma<<<grid, 256, G_SMEM>>>(p_cath, p_wprh, p_hbuf, DINNER, DMODEL, DMODEL);
    }

    // 7) residual + LayerNorm
    ln_kernel<<<M_ROWS, 256>>>(x, proj_b, ln_w, ln_b, out);
}

// round 5
// speedup vs baseline: 5.0898x; 2.4345x over previous
#include <cuda_runtime.h>
#include <cuda_fp16.h>
#include <math.h>
#include <stdint.h>

#define L_SEQ   1024
#define BATCH   2
#define DMODEL  1024
#define DINNER  2048
#define NHEADS  32
#define HEADDIM 64
#define DSTATE  64
#define CONVDIM 2176
#define DINPROJ 4256
#define DINPROJ_PAD 4352
#define M_ROWS  2048   // BATCH * L_SEQ

// ===================== scratch (device globals) =============================
__device__ float g_zx[2][M_ROWS * DINPROJ];
__device__ float g_xbc[2][M_ROWS * CONVDIM];
__device__ float g_dt[2][M_ROWS * NHEADS];
__device__ float g_dA[2][M_ROWS * NHEADS];
__device__ float g_y[2][M_ROWS * DINNER];
__device__ float g_hbuf[M_ROWS * DMODEL];

__device__ __half g_xh[2][M_ROWS * DMODEL];          // dir0 = x, dir1 = flip(x)
__device__ __half g_wip_h[2][DINPROJ_PAD * DMODEL];  // in_proj weights (padded rows)
__device__ __half g_yh[2][M_ROWS * DINNER];          // gated/normed y
__device__ __half g_woh[2][DMODEL * DINNER];         // out_proj weights
__device__ __half g_cath[M_ROWS * DINNER];           // concat(fwd, flip(bwd)), fp16
__device__ __half g_wprh[DMODEL * DINNER];           // final proj weights

// ===================== small helpers ========================================
__device__ __forceinline__ uint32_t h2_as_u32(__half2 h) {
    uint32_t u;
    *(__half2*)&u = h;
    return u;
}
__device__ __forceinline__ uint32_t smem_u32(const void* p) {
    uint32_t a;
    asm("{ .reg .u64 t; cvta.to.shared.u64 t, %1; cvt.u32.u64 %0, t; }" : "=r"(a) : "l"(p));
    return a;
}
__device__ __forceinline__ void cp_async16(uint32_t s, const void* g) {
    asm volatile("cp.async.cg.shared.global [%0], [%1], 16;" :: "r"(s), "l"(g));
}
__device__ __forceinline__ void cp_async4(uint32_t s, const void* g) {
    asm volatile("cp.async.ca.shared.global [%0], [%1], 4;" :: "r"(s), "l"(g));
}
__device__ __forceinline__ void cp_commit() { asm volatile("cp.async.commit_group;" ::: "memory"); }
__device__ __forceinline__ void ldmatrix4(uint32_t& r0, uint32_t& r1, uint32_t& r2, uint32_t& r3, uint32_t a) {
    asm volatile("ldmatrix.sync.aligned.m8n8.x4.shared.b16 {%0,%1,%2,%3}, [%4];"
                 : "=r"(r0), "=r"(r1), "=r"(r2), "=r"(r3) : "r"(a));
}
__device__ __forceinline__ void mma16816(float* c, const uint32_t* a, const uint32_t* b) {
    asm volatile("mma.sync.aligned.m16n8k16.row.col.f32.f16.f16.f32 "
                 "{%0,%1,%2,%3}, {%4,%5,%6,%7}, {%8,%9}, {%0,%1,%2,%3};"
                 : "+f"(c[0]), "+f"(c[1]), "+f"(c[2]), "+f"(c[3])
                 : "r"(a[0]), "r"(a[1]), "r"(a[2]), "r"(a[3]), "r"(b[0]), "r"(b[1]));
}
__device__ __forceinline__ int fliprow(int r) { return ((r >> 10) << 10) + (1023 - (r & 1023)); }

// ===================== fp32 -> fp16 converts (8 elems/thread) ==============
__global__ void cvt_x_kernel(const float* __restrict__ x) {
    int idx = blockIdx.x * blockDim.x + threadIdx.x;     // 8-elem group
    if (idx >= M_ROWS * DMODEL / 8) return;
    int row = idx >> 7, c8 = idx & 127;
    const float4* s = (const float4*)(x) + idx * 2;
    float4 v0 = s[0], v1 = s[1];
    uint4 o;
    o.x = h2_as_u32(__floats2half2_rn(v0.x, v0.y));
    o.y = h2_as_u32(__floats2half2_rn(v0.z, v0.w));
    o.z = h2_as_u32(__floats2half2_rn(v1.x, v1.y));
    o.w = h2_as_u32(__floats2half2_rn(v1.z, v1.w));
    ((uint4*)g_xh[0])[idx] = o;
    ((uint4*)g_xh[1])[fliprow(row) * 128 + c8] = o;
}

__global__ void cvt_w_kernel(const float* __restrict__ w, __half* __restrict__ dst,
                             int n8src, int n8tot) {
    int idx = blockIdx.x * blockDim.x + threadIdx.x;
    if (idx >= n8tot) return;
    uint4 o;
    if (idx < n8src) {
        const float4* s = (const float4*)(w) + idx * 2;
        float4 v0 = s[0], v1 = s[1];
        o.x = h2_as_u32(__floats2half2_rn(v0.x, v0.y));
        o.y = h2_as_u32(__floats2half2_rn(v0.z, v0.w));
        o.z = h2_as_u32(__floats2half2_rn(v1.x, v1.y));
        o.w = h2_as_u32(__floats2half2_rn(v1.z, v1.w));
    } else {
        o = make_uint4(0, 0, 0, 0);
    }
    ((uint4*)dst)[idx] = o;
}

// ===================== HMMA fp16 GEMM =======================================
// C[M,N] = A[M,K] @ B[N,K]^T. CTA 128x128, K-tile 64, 4-stage cp.async,
// register double-buffered ldmatrix frags. blockIdx.z selects direction.
// emode 0: fp32 C (bounds-checked on Nreal). emode 1: fp16 into g_cath with
//          row-flip for z==1 and column offset z*1024 (concat fusion).
#define KT 64
#define RS2 144                        // bytes per smem row (64 halves + 8 pad)
#define A_ST_BYTES (128 * RS2)         // 18432
#define ST_BYTES   (2 * A_ST_BYTES)    // 36864 per stage
#define NSTAGE 4
#define G_SMEM (NSTAGE * ST_BYTES)     // 147456

struct Frag { uint32_t A[2][4]; uint32_t B[8][2]; };

__device__ __forceinline__ void load_frags(uint32_t so, int k16,
        const uint32_t* a_off, const uint32_t* b_off, Frag& f) {
#pragma unroll
    for (int mi = 0; mi < 2; mi++)
        ldmatrix4(f.A[mi][0], f.A[mi][1], f.A[mi][2], f.A[mi][3], so + a_off[mi] + k16 * 32);
#pragma unroll
    for (int nj = 0; nj < 4; nj++) {
        uint32_t r0, r1, r2, r3;
        ldmatrix4(r0, r1, r2, r3, so + b_off[nj] + k16 * 32);
        f.B[2 * nj][0] = r0;     f.B[2 * nj][1] = r1;
        f.B[2 * nj + 1][0] = r2; f.B[2 * nj + 1][1] = r3;
    }
}

__global__ __launch_bounds__(256, 1) void gemm_hmma(
    const __half* __restrict__ A0, size_t strideA,
    const __half* __restrict__ B0, size_t strideB,
    float* __restrict__ C0, size_t strideC,
    int K, int Nreal, int ldc, int emode)
{
    extern __shared__ char smem[];
    const uint32_t sb = smem_u32(smem);
    const int tid = threadIdx.x;
    const int lane = tid & 31;
    const int warp = tid >> 5;
    const int z = blockIdx.z;
    const __half* A = A0 + (size_t)z * strideA;
    const __half* B = B0 + (size_t)z * strideB;
    float* C = C0 + (size_t)z * strideC;
    const int bm = blockIdx.y * 128;
    const int bn = blockIdx.x * 128;
    const int wm = (warp & 3) * 32;
    const int wn = (warp >> 2) * 64;
    const int T = K / KT;

    auto load_stage = [&](int t, int s) {
        const uint32_t so = sb + (uint32_t)s * ST_BYTES;
        const int k0 = t * KT;
#pragma unroll
        for (int it = 0; it < 4; it++) {
            int id = tid + (it << 8);
            int r = id >> 3, ck = id & 7;
            uint32_t sm = so + r * RS2 + ck * 16;
            cp_async16(sm, A + (size_t)(bm + r) * K + k0 + ck * 8);
            cp_async16(sm + A_ST_BYTES, B + (size_t)(bn + r) * K + k0 + ck * 8);
        }
    };

    float acc[2][8][4];
#pragma unroll
    for (int i = 0; i < 2; i++)
#pragma unroll
        for (int j = 0; j < 8; j++)
#pragma unroll
            for (int q = 0; q < 4; q++) acc[i][j][q] = 0.f;

    load_stage(0, 0); cp_commit();
    load_stage(1, 1); cp_commit();
    load_stage(2, 2); cp_commit();

    uint32_t a_off[2], b_off[4];
#pragma unroll
    for (int mi = 0; mi < 2; mi++)
        a_off[mi] = (wm + mi * 16 + (lane & 15)) * RS2 + ((lane >> 4) << 4);
#pragma unroll
    for (int nj = 0; nj < 4; nj++)
        b_off[nj] = (uint32_t)(wn + nj * 16 + (lane & 7) + ((lane >> 4) << 3)) * RS2
                  + (((lane >> 3) & 1) << 4) + A_ST_BYTES;

    Frag fr[2];
#pragma unroll 1
    for (int t = 0; t < T; t++) {
        asm volatile("cp.async.wait_group 2;" ::: "memory");
        __syncthreads();
        if (t + 3 < T) load_stage(t + 3, (t + 3) & 3);
        cp_commit();

        const uint32_t so = sb + (uint32_t)(t & 3) * ST_BYTES;
        load_frags(so, 0, a_off, b_off, fr[0]);
#pragma unroll
        for (int k16 = 0; k16 < 4; k16++) {
            if (k16 < 3) load_frags(so, k16 + 1, a_off, b_off, fr[(k16 + 1) & 1]);
            Frag& f = fr[k16 & 1];
#pragma unroll
            for (int mi = 0; mi < 2; mi++)
#pragma unroll
                for (int ni = 0; ni < 8; ni++)
                    mma16816(acc[mi][ni], f.A[mi], f.B[ni]);
        }
        __syncthreads();
    }

    if (emode == 0) {
#pragma unroll
        for (int mi = 0; mi < 2; mi++) {
            int row = bm + wm + mi * 16 + (lane >> 2);
#pragma unroll
            for (int ni = 0; ni < 8; ni++) {
                int col = bn + wn + ni * 8 + ((lane & 3) << 1);
                if (col < Nreal) {
                    *(float2*)&C[(size_t)row * ldc + col] = make_float2(acc[mi][ni][0], acc[mi][ni][1]);
                    *(float2*)&C[(size_t)(row + 8) * ldc + col] = make_float2(acc[mi][ni][2], acc[mi][ni][3]);
                }
            }
        }
    } else {
        // fused concat: fp16 store with row-flip for z==1, col offset z*1024
#pragma unroll
        for (int mi = 0; mi < 2; mi++) {
            int r0 = bm + wm + mi * 16 + (lane >> 2);
            int r1 = r0 + 8;
            int cr0 = z ? fliprow(r0) : r0;
            int cr1 = z ? fliprow(r1) : r1;
#pragma unroll
            for (int ni = 0; ni < 8; ni++) {
                int col = bn + wn + ni * 8 + ((lane & 3) << 1) + (z << 10);
                __half2 h0 = __floats2half2_rn(acc[mi][ni][0], acc[mi][ni][1]);
                __half2 h1 = __floats2half2_rn(acc[mi][ni][2], acc[mi][ni][3]);
                *(__half2*)&g_cath[(size_t)cr0 * DINNER + col] = h0;
                *(__half2*)&g_cath[(size_t)cr1 * DINNER + col] = h1;
            }
        }
    }
}

// ===================== fp32 recompute of dt columns =========================
__global__ __launch_bounds__(256) void fix_dt_kernel(const float* __restrict__ x,
        const float* __restrict__ fw, const float* __restrict__ bw) {
    __shared__ float xs[DMODEL];
    int blk = blockIdx.x;
    int dir = blk >> 11;
    int row = blk & 2047;
    int srow = dir ? fliprow(row) : row;
    ((float4*)xs)[threadIdx.x] = ((const float4*)(x + (size_t)srow * DMODEL))[threadIdx.x];
    __syncthreads();
    int warp = threadIdx.x >> 5, lane = threadIdx.x & 31;
    const float* w = dir ? bw : fw;
#pragma unroll
    for (int hh = 0; hh < 4; hh++) {
        int h = warp * 4 + hh;
        const float4* wr = (const float4*)(w + (size_t)(DINNER + CONVDIM + h) * DMODEL);
        const float4* xv = (const float4*)xs;
        float s = 0.f;
#pragma unroll
        for (int j = 0; j < 8; j++) {
            int i = lane + (j << 5);
            float4 a = xv[i], b = wr[i];
            s = fmaf(a.x, b.x, s); s = fmaf(a.y, b.y, s);
            s = fmaf(a.z, b.z, s); s = fmaf(a.w, b.w, s);
        }
#pragma unroll
        for (int o = 16; o; o >>= 1) s += __shfl_xor_sync(0xffffffffu, s, o);
        if (lane == 0) g_zx[dir][(size_t)row * DINPROJ + (DINNER + CONVDIM) + h] = s;
    }
}

// ===================== depthwise conv + silu (float4) =======================
__global__ void conv_silu(const float* __restrict__ fw, const float* __restrict__ fb,
                          const float* __restrict__ bw, const float* __restrict__ bb) {
    int idx = blockIdx.x * blockDim.x + threadIdx.x;   // float4 column groups
    if (idx >= 2 * M_ROWS * (CONVDIM / 4)) return;
    int c4 = idx % (CONVDIM / 4);
    int r = idx / (CONVDIM / 4);
    int dir = r >> 11;
    int row = r & 2047;
    int t = row & 1023;
    int c = c4 * 4;
    const float* w = dir ? bw : fw;
    const float* bias = dir ? bb : fb;
    const float* zx = g_zx[dir];
    float4 acc = *(const float4*)(bias + c);
#pragma unroll
    for (int j = 0; j < 4; j++) {
        int tj = t - 3 + j;
        if (tj >= 0) {
            float4 wv = *(const float4*)(w + j * CONVDIM + c);
            float4 xv = *(const float4*)(zx + (size_t)(row - 3 + j) * DINPROJ + DINNER + c);
            acc.x = fmaf(wv.x, xv.x, acc.x); acc.y = fmaf(wv.y, xv.y, acc.y);
            acc.z = fmaf(wv.z, xv.z, acc.z); acc.w = fmaf(wv.w, xv.w, acc.w);
        }
    }
    acc.x /= (1.f + expf(-acc.x)); acc.y /= (1.f + expf(-acc.y));
    acc.z /= (1.f + expf(-acc.z)); acc.w /= (1.f + expf(-acc.w));
    *(float4*)(&g_xbc[dir][(size_t)row * CONVDIM + c]) = acc;
}

// ===================== dt / dA =============================================
__global__ void dt_kernel(const float* __restrict__ f_dtb, const float* __restrict__ f_alog,
                          const float* __restrict__ b_dtb, const float* __restrict__ b_alog) {
    int idx = blockIdx.x * blockDim.x + threadIdx.x;
    if (idx >= 2 * M_ROWS * NHEADS) return;
    int h = idx & 31;
    int r = idx >> 5;
    int dir = r >> 11;
    int row = r & 2047;
    const float* db = dir ? b_dtb : f_dtb;
    const float* al = dir ? b_alog : f_alog;
    float xr = g_zx[dir][(size_t)row * DINPROJ + (DINNER + CONVDIM) + h] + db[h];
    float dt = (xr > 20.f) ? xr : log1pf(expf(xr));
    float A = -expf(al[h]);
    g_dt[dir][row * NHEADS + h] = dt;
    g_dA[dir][row * NHEADS + h] = expf(dt * A);
}

// ===================== SSM scan (smem-staged, double-buffered) ==============
#define SCH 8   // taus per chunk
__global__ __launch_bounds__(256) void scan_kernel() {
    __shared__ float sBC[2][SCH][160];   // 8 groups of 16 floats padded to 20
    __shared__ float sX[2][SCH][64];
    __shared__ float sS[2][SCH][2];      // [0]=dA [1]=dt

    int blk = blockIdx.x;
    int dir = blk >> 6;
    int b = (blk >> 5) & 1;
    int h = blk & 31;
    int t = threadIdx.x;
    int p = t >> 2;
    int s = t & 3;

    const float* xbc = g_xbc[dir] + (size_t)(b * L_SEQ) * CONVDIM;
    const float* dtb = g_dt[dir] + (size_t)(b * L_SEQ) * NHEADS + h;
    const float* dAb = g_dA[dir] + (size_t)(b * L_SEQ) * NHEADS + h;
    float* yout = g_y[dir] + (size_t)(b * L_SEQ) * DINNER + h * HEADDIM + p;

    auto prefetch = [&](int cc) {
        int bf = cc & 1;
#pragma unroll
        for (int i = 0; i < 2; i++) {
            int op = t + (i << 8);
            if (op < 384) {
                int tau = op / 48, j = op - tau * 48;
                int gtau = cc * SCH + tau;
                if (j < 32) {
                    int g = j >> 2;
                    cp_async16(smem_u32(&sBC[bf][tau][g * 20 + (j & 3) * 4]),
                               xbc + (size_t)gtau * CONVDIM + DINNER + j * 4);
                } else {
                    int jj = j - 32;
                    cp_async16(smem_u32(&sX[bf][tau][jj * 4]),
                               xbc + (size_t)gtau * CONVDIM + h * HEADDIM + jj * 4);
                }
            }
        }
        if (t < 16) {
            int tau = t >> 1;
            int gtau = cc * SCH + tau;
            const float* src = (t & 1) ? (dtb + gtau * NHEADS) : (dAb + gtau * NHEADS);
            cp_async4(smem_u32(&sS[bf][tau][t & 1]), src);
        }
    };

    float st[16];
#pragma unroll
    for (int i = 0; i < 16; i++) st[i] = 0.f;

    prefetch(0); cp_commit();
    prefetch(1); cp_commit();

#pragma unroll 1
    for (int cc = 0; cc < L_SEQ / SCH; cc++) {
        asm volatile("cp.async.wait_group 1;" ::: "memory");
        __syncthreads();
        int bf = cc & 1;
#pragma unroll
        for (int tl = 0; tl < SCH; tl++) {
            float dAv = sS[bf][tl][0];
            float dtv = sS[bf][tl][1];
            float xv  = sX[bf][tl][p];
            float coef = dtv * xv;
            const float4* Bp = (const float4*)&sBC[bf][tl][s * 20];
            const float4* Cp = (const float4*)&sBC[bf][tl][(4 + s) * 20];
            float4 B0 = Bp[0], B1 = Bp[1], B2 = Bp[2], B3 = Bp[3];
            float4 C0 = Cp[0], C1 = Cp[1], C2 = Cp[2], C3 = Cp[3];
            float acc = 0.f;
            st[ 0] = fmaf(st[ 0], dAv, coef * B0.x); acc = fmaf(st[ 0], C0.x, acc);
            st[ 1] = fmaf(st[ 1], dAv, coef * B0.y); acc = fmaf(st[ 1], C0.y, acc);
            st[ 2] = fmaf(st[ 2], dAv, coef * B0.z); acc = fmaf(st[ 2], C0.z, acc);
            st[ 3] = fmaf(st[ 3], dAv, coef * B0.w); acc = fmaf(st[ 3], C0.w, acc);
            st[ 4] = fmaf(st[ 4], dAv, coef * B1.x); acc = fmaf(st[ 4], C1.x, acc);
            st[ 5] = fmaf(st[ 5], dAv, coef * B1.y); acc = fmaf(st[ 5], C1.y, acc);
            st[ 6] = fmaf(st[ 6], dAv, coef * B1.z); acc = fmaf(st[ 6], C1.z, acc);
            st[ 7] = fmaf(st[ 7], dAv, coef * B1.w); acc = fmaf(st[ 7], C1.w, acc);
            st[ 8] = fmaf(st[ 8], dAv, coef * B2.x); acc = fmaf(st[ 8], C2.x, acc);
            st[ 9] = fmaf(st[ 9], dAv, coef * B2.y); acc = fmaf(st[ 9], C2.y, acc);
            st[10] = fmaf(st[10], dAv, coef * B2.z); acc = fmaf(st[10], C2.z, acc);
            st[11] = fmaf(st[11], dAv, coef * B2.w); acc = fmaf(st[11], C2.w, acc);
            st[12] = fmaf(st[12], dAv, coef * B3.x); acc = fmaf(st[12], C3.x, acc);
            st[13] = fmaf(st[13], dAv, coef * B3.y); acc = fmaf(st[13], C3.y, acc);
            st[14] = fmaf(st[14], dAv, coef * B3.z); acc = fmaf(st[14], C3.z, acc);
            st[15] = fmaf(st[15], dAv, coef * B3.w); acc = fmaf(st[15], C3.w, acc);
            acc += __shfl_xor_sync(0xffffffffu, acc, 1);
            acc += __shfl_xor_sync(0xffffffffu, acc, 2);
            if (s == 0) yout[(size_t)(cc * SCH + tl) * DINNER] = acc;
        }
        __syncthreads();
        if (cc + 2 < L_SEQ / SCH) prefetch(cc + 2);
        cp_commit();
    }
}

// ===================== gate + RMSNorm -> fp16 (float4) ======================
__global__ __launch_bounds__(256) void gate_rms(const float* __restrict__ fD, const float* __restrict__ frms,
                                                const float* __restrict__ bD, const float* __restrict__ brms) {
    int blk = blockIdx.x;
    int dir = blk >> 11;
    int row = blk & 2047;
    const float* Dp = dir ? bD : fD;
    const float* rw = dir ? brms : frms;
    const float4* zr = (const float4*)(g_zx[dir] + (size_t)row * DINPROJ);
    const float4* xr = (const float4*)(g_xbc[dir] + (size_t)row * CONVDIM);
    const float4* yr = (const float4*)(g_y[dir] + (size_t)row * DINNER);

    float vals[8];
    float ss = 0.f;
#pragma unroll
    for (int i = 0; i < 2; i++) {
        int g = threadIdx.x + (i << 8);
        float4 y4 = yr[g], z4 = zr[g], x4 = xr[g];
        float Dv = Dp[(g * 4) >> 6];
        float yv, zv;
        yv = fmaf(Dv, x4.x, y4.x); zv = z4.x; yv *= zv / (1.f + expf(-zv)); vals[i*4+0] = yv; ss = fmaf(yv, yv, ss);
        yv = fmaf(Dv, x4.y, y4.y); zv = z4.y; yv *= zv / (1.f + expf(-zv)); vals[i*4+1] = yv; ss = fmaf(yv, yv, ss);
        yv = fmaf(Dv, x4.z, y4.z); zv = z4.z; yv *= zv / (1.f + expf(-zv)); vals[i*4+2] = yv; ss = fmaf(yv, yv, ss);
        yv = fmaf(Dv, x4.w, y4.w); zv = z4.w; yv *= zv / (1.f + expf(-zv)); vals[i*4+3] = yv; ss = fmaf(yv, yv, ss);
    }
    __shared__ float red[8];
    __shared__ float s_scale;
#pragma unroll
    for (int o = 16; o; o >>= 1) ss += __shfl_xor_sync(0xffffffffu, ss, o);
    if ((threadIdx.x & 31) == 0) red[threadIdx.x >> 5] = ss;
    __syncthreads();
    if (threadIdx.x == 0) {
        float tot = 0.f;
#pragma unroll
        for (int i = 0; i < 8; i++) tot += red[i];
        s_scale = rsqrtf(tot / (float)DINNER + 1e-5f);
    }
    __syncthreads();
    float sc = s_scale;
#pragma unroll
    for (int i = 0; i < 2; i++) {
        int g = threadIdx.x + (i << 8);
        const float4 w4 = ((const float4*)rw)[g];
        float o0 = vals[i*4+0] * sc * w4.x;
        float o1 = vals[i*4+1] * sc * w4.y;
        float o2 = vals[i*4+2] * sc * w4.z;
        float o3 = vals[i*4+3] * sc * w4.w;
        uint2 st;
        st.x = h2_as_u32(__floats2half2_rn(o0, o1));
        st.y = h2_as_u32(__floats2half2_rn(o2, o3));
        ((uint2*)(g_yh[dir] + (size_t)row * DINNER))[g] = st;
    }
}

// ===================== residual + LayerNorm ================================
__global__ __launch_bounds__(256) void ln_kernel(const float* __restrict__ x,
        const float* __restrict__ pb, const float* __restrict__ lw,
        const float* __restrict__ lb, float* __restrict__ out) {
    int row = blockIdx.x;
    const float* hr = g_hbuf + (size_t)row * DMODEL;
    const float* xr = x + (size_t)row * DMODEL;
    float v[4];
    float sum = 0.f;
#pragma unroll
    for (int i = 0; i < 4; i++) {
        int c = threadIdx.x + (i << 8);
        v[i] = hr[c] + xr[c] + pb[c];
        sum += v[i];
    }
    __shared__ float red[8];
    __shared__ float s_mu, s_inv;
#pragma unroll
    for (int o = 16; o; o >>= 1) sum += __shfl_xor_sync(0xffffffffu, sum, o);
    if ((threadIdx.x & 31) == 0) red[threadIdx.x >> 5] = sum;
    __syncthreads();
    if (threadIdx.x == 0) {
        float tot = 0.f;
#pragma unroll
        for (int i = 0; i < 8; i++) tot += red[i];
        s_mu = tot / (float)DMODEL;
    }
    __syncthreads();
    float mu = s_mu;
    float vs = 0.f;
#pragma unroll
    for (int i = 0; i < 4; i++) { float d = v[i] - mu; vs = fmaf(d, d, vs); }
#pragma unroll
    for (int o = 16; o; o >>= 1) vs += __shfl_xor_sync(0xffffffffu, vs, o);
    if ((threadIdx.x & 31) == 0) red[threadIdx.x >> 5] = vs;
    __syncthreads();
    if (threadIdx.x == 0) {
        float tot = 0.f;
#pragma unroll
        for (int i = 0; i < 8; i++) tot += red[i];
        s_inv = rsqrtf(tot / (float)DMODEL + 1e-5f);
    }
    __syncthreads();
    float inv = s_inv;
#pragma unroll
    for (int i = 0; i < 4; i++) {
        int c = threadIdx.x + (i << 8);
        out[(size_t)row * DMODEL + c] = (v[i] - mu) * inv * lw[c] + lb[c];
    }
}

// ===================== host orchestration ===================================
extern "C" void kernel_launch(void* const* d_in, const int* in_sizes, int n_in,
                              void* d_out, int out_size) {
    const float* x            = (const float*)d_in[0];
    const float* f_in_proj_w  = (const float*)d_in[1];
    const float* f_conv_w     = (const float*)d_in[2];
    const float* f_conv_b     = (const float*)d_in[3];
    const float* f_dt_bias    = (const float*)d_in[4];
    const float* f_A_log      = (const float*)d_in[5];
    const float* f_D          = (const float*)d_in[6];
    const float* f_rms_w      = (const float*)d_in[7];
    const float* f_out_proj_w = (const float*)d_in[8];
    const float* b_in_proj_w  = (const float*)d_in[9];
    const float* b_conv_w     = (const float*)d_in[10];
    const float* b_conv_b     = (const float*)d_in[11];
    const float* b_dt_bias    = (const float*)d_in[12];
    const float* b_A_log      = (const float*)d_in[13];
    const float* b_D          = (const float*)d_in[14];
    const float* b_rms_w      = (const float*)d_in[15];
    const float* b_out_proj_w = (const float*)d_in[16];
    const float* proj_w       = (const float*)d_in[17];
    const float* proj_b       = (const float*)d_in[18];
    const float* ln_w         = (const float*)d_in[19];
    const float* ln_b         = (const float*)d_in[20];
    float* out = (float*)d_out;

    float *p_zx, *p_hbuf;
    __half *p_xh, *p_wip, *p_yh, *p_woh, *p_cath, *p_wprh;
    cudaGetSymbolAddress((void**)&p_zx, g_zx);
    cudaGetSymbolAddress((void**)&p_hbuf, g_hbuf);
    cudaGetSymbolAddress((void**)&p_xh, g_xh);
    cudaGetSymbolAddress((void**)&p_wip, g_wip_h);
    cudaGetSymbolAddress((void**)&p_yh, g_yh);
    cudaGetSymbolAddress((void**)&p_woh, g_woh);
    cudaGetSymbolAddress((void**)&p_cath, g_cath);
    cudaGetSymbolAddress((void**)&p_wprh, g_wprh);

    cudaFuncSetAttribute(gemm_hmma, cudaFuncAttributeMaxDynamicSharedMemorySize, G_SMEM);

    const size_t XSZ  = (size_t)M_ROWS * DMODEL;
    const size_t WIPS = (size_t)DINPROJ_PAD * DMODEL;
    const size_t YSZ  = (size_t)M_ROWS * DINNER;
    const size_t WOS  = (size_t)DMODEL * DINNER;

    // 0) converts (8 elems/thread)
    cvt_x_kernel<<<(int)(XSZ / 8 / 256), 256>>>(x);
    cvt_w_kernel<<<(int)((WIPS / 8 + 255) / 256), 256>>>(f_in_proj_w, p_wip,        DINPROJ * DMODEL / 8, (int)(WIPS / 8));
    cvt_w_kernel<<<(int)((WIPS / 8 + 255) / 256), 256>>>(b_in_proj_w, p_wip + WIPS, DINPROJ * DMODEL / 8, (int)(WIPS / 8));
    cvt_w_kernel<<<(int)(WOS / 8 / 256), 256>>>(f_out_proj_w, p_woh,       (int)(WOS / 8), (int)(WOS / 8));
    cvt_w_kernel<<<(int)(WOS / 8 / 256), 256>>>(b_out_proj_w, p_woh + WOS, (int)(WOS / 8), (int)(WOS / 8));
    cvt_w_kernel<<<(int)(WOS / 8 / 256), 256>>>(proj_w,       p_wprh,      (int)(WOS / 8), (int)(WOS / 8));

    // 1) in_proj GEMMs merged over z: (2048,1024)@(4352,1024)^T -> g_zx
    {
        dim3 grid(DINPROJ_PAD / 128, M_ROWS / 128, 2);
        gemm_hmma<<<grid, 256, G_SMEM>>>(p_xh, XSZ, p_wip, WIPS, p_zx, (size_t)M_ROWS * DINPROJ,
                                         DMODEL, DINPROJ, DINPROJ, 0);
    }

    // 1b) fp32 recompute of dt columns
    fix_dt_kernel<<<2 * M_ROWS, 256>>>(x, f_in_proj_w, b_in_proj_w);

    // 2) conv + silu; dt / dA
    conv_silu<<<(2 * M_ROWS * (CONVDIM / 4) + 255) / 256, 256>>>(f_conv_w, f_conv_b, b_conv_w, b_conv_b);
    dt_kernel<<<(2 * M_ROWS * NHEADS + 255) / 256, 256>>>(f_dt_bias, f_A_log, b_dt_bias, b_A_log);

    // 3) scan (smem staged)
    scan_kernel<<<128, 256>>>();

    // 4) gate + rmsnorm -> fp16
    gate_rms<<<2 * M_ROWS, 256>>>(f_D, f_rms_w, b_D, b_rms_w);

    // 5) out_proj GEMMs merged over z, epilogue writes fp16 concat (flipped)
    {
        dim3 grid(DMODEL / 128, M_ROWS / 128, 2);
        gemm_hmma<<<grid, 256, G_SMEM>>>(p_yh, YSZ, p_woh, WOS, (float*)nullptr, 0,
                                         DINNER, DMODEL, DMODEL, 1);
    }

    // 6) final proj GEMM: (2048,2048)@(1024,2048)^T -> g_hbuf
    {
        dim3 grid(DMODEL / 128, M_ROWS / 128, 1);
        gemm_hmma<<<grid, 256, G_SMEM>>>(p_cath, 0, p_wprh, 0, p_hbuf, 0,
                                         DINNER, DMODEL, DMODEL, 0);
    }

    // 7) residual + LayerNorm
    ln_kernel<<<M_ROWS, 256>>>(x, proj_b, ln_w, ln_b, out);
}